// round 10
// baseline (speedup 1.0000x reference)
#include <cuda_runtime.h>
#include <cuda_bf16.h>
#include <math.h>
#include <stdint.h>

#define BATCH 128
#define CELLS 1024
#define XROWS 1025            // cells + meta
#define GROWS 1026            // + MAgg row
#define FDIM  128
#define MTOT  (BATCH*GROWS)   // 131328

typedef unsigned long long u64;
union F2 { u64 u; float2 f; };

__device__ __forceinline__ u64 pack2(float lo, float hi){
    u64 r; asm("mov.b64 %0, {%1, %2};" : "=l"(r) : "f"(lo), "f"(hi)); return r;
}
__device__ __forceinline__ void ffma2(u64& d, u64 a, u64 b){
    asm("fma.rn.f32x2 %0, %1, %2, %0;" : "+l"(d) : "l"(a), "l"(b));
}
__device__ __forceinline__ float elu1(float v){ return v > 0.f ? v : (expf(v) - 1.f); }
__device__ __forceinline__ uint32_t smem_u32(const void* p){
    uint32_t a; asm("{ .reg .u64 t; cvta.to.shared.u64 t, %1; cvt.u32.u64 %0, t; }" : "=r"(a) : "l"(p));
    return a;
}
#define CP16(dst, src) asm volatile("cp.async.cg.shared.global [%0], [%1], 16;" :: "r"(dst), "l"(src))
#define CP_COMMIT()    asm volatile("cp.async.commit_group;")
#define CP_WAIT0()     asm volatile("cp.async.wait_group 0;" ::: "memory")

// ---------------- scratch ----------------
__device__ __nv_bfloat16 g_xb0[(size_t)BATCH*XROWS*FDIM];
__device__ __nv_bfloat16 g_xb1[(size_t)BATCH*XROWS*FDIM];
__device__ __nv_bfloat16 g_uv[(size_t)BATCH*GROWS*256];   // 0-127: u, 128-255: v
__device__ float g_ms0[BATCH*FDIM];   // fp32 per-batch cell sums (ping)
__device__ float g_ms1[BATCH*FDIM];   // (pong)
__device__ __nv_bfloat16 g_wt[3*256*128];
__device__ float g_state[BATCH*640];
__device__ float g_h1[BATCH*512];
__device__ float g_h2[BATCH*512];
__device__ float g_ft[BATCH*256];
__device__ float g_p1[BATCH*256];
__device__ float g_p2[BATCH*256];

// ---------------- weight prep: Wt[l][n'][k] ----------------
__global__ void prep_wt(const float* __restrict__ Ws, const float* __restrict__ Wn,
                        __nv_bfloat16* __restrict__ Wt){
    int idx = blockIdx.x * blockDim.x + threadIdx.x;
    int l = idx >> 15;
    int r = idx & 32767;
    int n = r >> 7;
    int k = r & 127;
    float v = (n < 128) ? Ws[l*16384 + k*128 + n] : Wn[l*16384 + k*128 + (n-128)];
    Wt[idx] = __float2bfloat16(v);
}

// ---------------- layer-0 meta aggregation (gmap fp32 -> fp32 sums) ----------------
__global__ void meta_agg0(const float* __restrict__ G, float* __restrict__ MSum){
    __shared__ float2 sm[16][64];
    int b = blockIdx.x, t = threadIdx.x;   // 1024 threads
    int f2 = t & 63, p = t >> 6;
    float2 s = make_float2(0.f, 0.f);
    const float2* gb = (const float2*)(G + (size_t)b * CELLS * FDIM);
    int c0 = p * 64;
    #pragma unroll 8
    for (int c = c0; c < c0 + 64; c++) {
        float2 v = gb[c*64 + f2];
        s.x += v.x; s.y += v.y;
    }
    sm[p][f2] = s;
    __syncthreads();
    if (p == 0) {
        s = sm[0][f2];
        #pragma unroll
        for (int i = 1; i < 16; i++) { s.x += sm[i][f2].x; s.y += sm[i][f2].y; }
        ((float2*)MSum)[b*64 + f2] = s;
    }
}

// ---------------- dense GEMM: UV = A @ Wt^T (+bias on u-half) ----------------
// CTA tile 128(M) x 256(N, both halves) via two MMA passes over shared A tile.
// 512 threads = 16 warps (4m x 4n), warp tile 32x32 per pass.
#define STR2 272
#define SMB2_OFF (128*STR2)
#define GEMM_SMEM (128*STR2 + 256*STR2)   // 104448

__device__ __forceinline__ void ldmA(uint32_t addr, uint32_t* r){
    asm volatile("ldmatrix.sync.aligned.m8n8.x4.shared.b16 {%0,%1,%2,%3}, [%4];"
        : "=r"(r[0]), "=r"(r[1]), "=r"(r[2]), "=r"(r[3]) : "r"(addr));
}

__global__ void __launch_bounds__(512, 2) gnn_gemm(
    const __nv_bfloat16* __restrict__ X, const float* __restrict__ G, int srcF32,
    const float* __restrict__ MSumIn, float* __restrict__ MSumZero,
    const __nv_bfloat16* __restrict__ Wt, const float* __restrict__ bias,
    __nv_bfloat16* __restrict__ UV)
{
    extern __shared__ char smem[];
    uint32_t sb = smem_u32(smem);
    int t = threadIdx.x;
    int wid = t >> 5, lane = t & 31;
    int m0cta = blockIdx.x * 128;

    // ---- zero next-layer MSum buffer (stream-ordered before stencil atomics) ----
    if (blockIdx.x < 16) {
        ((float2*)MSumZero)[blockIdx.x * 512 + t] = make_float2(0.f, 0.f);
    }

    // ---- B tile: 256 n-rows x 128 k; thread: n = t>>1, half h = t&1 (8x16B) ----
    {
        int n = t >> 1, h = t & 1;
        const char* src = (const char*)(Wt + (size_t)n*128 + h*64);
        uint32_t dst = sb + SMB2_OFF + n*STR2 + h*128;
        #pragma unroll
        for (int j = 0; j < 8; j++) CP16(dst + j*16, src + j*16);
    }
    // ---- A tile: 128 rows x 128 k; thread: m = t>>2, quarter qh = t&3 ----
    {
        int m = t >> 2, qh = t & 3;
        int row = m0cta + m;
        int b = row / GROWS;
        int node = row - b * GROWS;
        uint32_t dst = sb + m*STR2 + qh*64;
        if (node == GROWS - 1) {
            // MAgg row from fp32 sums
            const float* src = MSumIn + b*FDIM + qh*32;
            #pragma unroll
            for (int j = 0; j < 4; j++) {
                float4 v0 = *(const float4*)(src + j*8);
                float4 v1 = *(const float4*)(src + j*8 + 4);
                uint4 o;
                __nv_bfloat162* ho = (__nv_bfloat162*)&o;
                ho[0] = __float22bfloat162_rn(make_float2(v0.x, v0.y));
                ho[1] = __float22bfloat162_rn(make_float2(v0.z, v0.w));
                ho[2] = __float22bfloat162_rn(make_float2(v1.x, v1.y));
                ho[3] = __float22bfloat162_rn(make_float2(v1.z, v1.w));
                *(uint4*)(smem + m*STR2 + qh*64 + j*16) = o;
            }
        } else if (!srcF32) {
            const char* src = (const char*)(X + ((size_t)b * XROWS + node) * FDIM + qh*32);
            #pragma unroll
            for (int j = 0; j < 4; j++) CP16(dst + j*16, src + j*16);
        } else {
            if (node < CELLS) {
                const float* src = G + ((size_t)b * CELLS + node) * FDIM + qh*32;
                #pragma unroll
                for (int j = 0; j < 4; j++) {
                    float4 v0 = *(const float4*)(src + j*8);
                    float4 v1 = *(const float4*)(src + j*8 + 4);
                    uint4 o;
                    __nv_bfloat162* ho = (__nv_bfloat162*)&o;
                    ho[0] = __float22bfloat162_rn(make_float2(v0.x, v0.y));
                    ho[1] = __float22bfloat162_rn(make_float2(v0.z, v0.w));
                    ho[2] = __float22bfloat162_rn(make_float2(v1.x, v1.y));
                    ho[3] = __float22bfloat162_rn(make_float2(v1.z, v1.w));
                    *(uint4*)(smem + m*STR2 + qh*64 + j*16) = o;
                }
            } else {   // meta node: x == 0 at layer 0
                uint4 z = make_uint4(0,0,0,0);
                #pragma unroll
                for (int j = 0; j < 4; j++) *(uint4*)(smem + m*STR2 + qh*64 + j*16) = z;
            }
        }
    }
    CP_COMMIT();
    CP_WAIT0();
    __syncthreads();

    // ---- MMA: two passes (u half, v half) over the same A tile ----
    int warp_m = wid >> 2;   // 0-3
    int warp_n = wid & 3;    // 0-3
    uint32_t saA = sb + (warp_m*32 + (lane & 15))*STR2 + (lane >> 4)*16;
    int gr = lane >> 2, gc = lane & 3;

    #pragma unroll
    for (int nhalf = 0; nhalf < 2; nhalf++) {
        uint32_t saB = sb + SMB2_OFF
                     + (nhalf*128 + warp_n*32 + (lane >> 4)*8 + (lane & 7))*STR2
                     + ((lane >> 3) & 1)*16;

        float acc[2][4][4];
        #pragma unroll
        for (int i = 0; i < 2; i++)
            #pragma unroll
            for (int j = 0; j < 4; j++)
                #pragma unroll
                for (int q = 0; q < 4; q++) acc[i][j][q] = 0.f;

        #pragma unroll
        for (int ks = 0; ks < 8; ks++) {
            uint32_t ko = ks * 32;
            uint32_t a0[4], a1[4], b0[4], b1[4];
            ldmA(saA + ko, a0);
            ldmA(saA + 16*STR2 + ko, a1);
            ldmA(saB + ko, b0);
            ldmA(saB + 16*STR2 + ko, b1);
            uint32_t* afr[2] = { a0, a1 };
            uint32_t* bfr[2] = { b0, b1 };
            #pragma unroll
            for (int mf = 0; mf < 2; mf++)
                #pragma unroll
                for (int nf = 0; nf < 4; nf++) {
                    uint32_t rb0 = bfr[nf >> 1][(nf & 1)*2];
                    uint32_t rb1 = bfr[nf >> 1][(nf & 1)*2 + 1];
                    asm volatile("mma.sync.aligned.m16n8k16.row.col.f32.bf16.bf16.f32 "
                        "{%0,%1,%2,%3}, {%4,%5,%6,%7}, {%8,%9}, {%0,%1,%2,%3};"
                        : "+f"(acc[mf][nf][0]), "+f"(acc[mf][nf][1]),
                          "+f"(acc[mf][nf][2]), "+f"(acc[mf][nf][3])
                        : "r"(afr[mf][0]), "r"(afr[mf][1]), "r"(afr[mf][2]), "r"(afr[mf][3]),
                          "r"(rb0), "r"(rb1));
                }
        }

        // epilogue for this half
        #pragma unroll
        for (int nf = 0; nf < 4; nf++) {
            int coln = warp_n*32 + nf*8 + 2*gc;
            float2 bb = make_float2(0.f, 0.f);
            if (nhalf == 0) bb = *(const float2*)(bias + coln);
            int colg = nhalf*128 + coln;
            #pragma unroll
            for (int mf = 0; mf < 2; mf++) {
                size_t r0 = (size_t)m0cta + warp_m*32 + mf*16 + gr;
                float v0 = acc[mf][nf][0] + bb.x;
                float v1 = acc[mf][nf][1] + bb.y;
                float v2 = acc[mf][nf][2] + bb.x;
                float v3 = acc[mf][nf][3] + bb.y;
                *(__nv_bfloat162*)(UV + r0 * 256 + colg)       = __float22bfloat162_rn(make_float2(v0, v1));
                *(__nv_bfloat162*)(UV + (r0 + 8) * 256 + colg) = __float22bfloat162_rn(make_float2(v2, v3));
            }
        }
    }
}

// ---------------- stencil + fused batch-sum: y = elu(u + v[meta] + sum v[nbrs]) ----------------
__device__ __forceinline__ void badd8(const __nv_bfloat16* p, __nv_bfloat162* s){
    uint4 v = *(const uint4*)p;
    __nv_bfloat162* h = (__nv_bfloat162*)&v;
    #pragma unroll
    for (int i = 0; i < 4; i++) s[i] = __hadd2(s[i], h[i]);
}

// grid: (65, BATCH), 256 threads: node = bx*16 + (tid>>4), chunk q = tid&15
__global__ void gnn_stencil(const __nv_bfloat16* __restrict__ UV, __nv_bfloat16* __restrict__ Y,
                            float* __restrict__ MSumOut)
{
    __shared__ float sred[256][8];
    int b = blockIdx.y;
    int tid = threadIdx.x;
    int node = blockIdx.x * 16 + (tid >> 4);
    int q = tid & 15;
    bool valid = node < XROWS;

    float f[8];
    #pragma unroll
    for (int i = 0; i < 8; i++) f[i] = 0.f;

    if (valid) {
        const __nv_bfloat16* uvb = UV + (size_t)b * GROWS * 256;
        int qo = q * 8;
        __nv_bfloat162 s[4];
        {   // u
            uint4 v = *(const uint4*)(uvb + (size_t)node*256 + qo);
            __nv_bfloat162* h = (__nv_bfloat162*)&v;
            #pragma unroll
            for (int i = 0; i < 4; i++) s[i] = h[i];
        }
        const __nv_bfloat16* vb = uvb + 128 + qo;
        if (node < CELLS) {
            badd8(vb + (size_t)CELLS*256, s);       // v[meta]
            int r = node >> 5, c = node & 31;
            if (r > 0)  badd8(vb + (size_t)(node-32)*256, s);
            if (r < 31) badd8(vb + (size_t)(node+32)*256, s);
            if (c > 0)  badd8(vb + (size_t)(node-1)*256, s);
            if (c < 31) badd8(vb + (size_t)(node+1)*256, s);
        } else {
            badd8(vb + (size_t)(CELLS+1)*256, s);   // v[MAgg row]
        }
        uint4 o;
        __nv_bfloat162* ho = (__nv_bfloat162*)&o;
        #pragma unroll
        for (int i = 0; i < 4; i++) {
            float2 fv = __bfloat1622float2(s[i]);
            float e0 = elu1(fv.x), e1 = elu1(fv.y);
            ho[i] = __float22bfloat162_rn(make_float2(e0, e1));
            if (node < CELLS) { f[2*i] = e0; f[2*i+1] = e1; }
        }
        *(uint4*)(Y + ((size_t)b * XROWS + node) * FDIM + qo) = o;
    }

    // block reduce over the 16 nodes (same q: stride 16 in tid space)
    #pragma unroll
    for (int i = 0; i < 8; i++) sred[tid][i] = f[i];
    __syncthreads();
    #pragma unroll
    for (int off = 128; off >= 16; off >>= 1) {
        if (tid < off) {
            #pragma unroll
            for (int i = 0; i < 8; i++) sred[tid][i] += sred[tid + off][i];
        }
        __syncthreads();
    }
    if (tid < 16) {
        #pragma unroll
        for (int i = 0; i < 8; i++)
            atomicAdd(&MSumOut[b*FDIM + tid*8 + i], sred[tid][i]);
    }
}

// ---------------- gather 5 cells ----------------
__global__ void gather_state(const __nv_bfloat16* __restrict__ X, const int* __restrict__ pos,
                             float* __restrict__ state)
{
    int b = blockIdx.x;
    int f = threadIdx.x;
    int r = pos[2*b + 0];
    int c = pos[2*b + 1];
    const int dr[5] = {-1, 0, 1, 0, 0};
    const int dc[5] = { 0,-1, 0, 1, 0};
    #pragma unroll
    for (int o = 0; o < 5; o++) {
        int j  = (r + dr[o] + 1) * 32 + (c + dc[o] + 1);
        int jr = j / 34, jc = j % 34;
        float v = 0.f;
        if (jr >= 1 && jr <= 32 && jc >= 1 && jc <= 32) {
            int cell = (jr - 1) * 32 + (jc - 1);
            v = __bfloat162float(X[((size_t)b * XROWS + cell) * FDIM + f]);
        }
        state[b * 640 + o * FDIM + f] = v;
    }
}

// ---------------- small MLP GEMM (fp32, f32x2), tile 32x64 ----------------
template<bool ELU>
__global__ void __launch_bounds__(256) mlp_gemm(
    const float* __restrict__ A, const float* __restrict__ W,
    const float* __restrict__ bias, float* __restrict__ C, int K, int N)
{
    __shared__ float sAm[32][36];
    __shared__ float sWm[32][68];
    int t = threadIdx.x;
    int tx = t & 15;          // cols tx*4
    int ty = t >> 4;          // rows ty*2, ty*2+1
    int m0 = blockIdx.y * 32;
    int n0 = blockIdx.x * 64;

    u64 acc[2][2];
    acc[0][0] = acc[0][1] = acc[1][0] = acc[1][1] = 0ULL;

    int arow = t >> 3, acg = t & 7;
    int wr = t >> 4, wn = (t & 15) * 4;

    for (int kk = 0; kk < K; kk += 32) {
        *(float4*)&sAm[arow][acg*4] = *(const float4*)(A + (size_t)(m0 + arow) * K + kk + acg*4);
        *(float4*)&sWm[wr][wn]      = *(const float4*)(W + (size_t)(kk + wr) * N + n0 + wn);
        *(float4*)&sWm[wr+16][wn]   = *(const float4*)(W + (size_t)(kk + wr + 16) * N + n0 + wn);
        __syncthreads();
        #pragma unroll
        for (int k = 0; k < 32; k++) {
            F2 b0, b1;
            b0.f = *(const float2*)&sWm[k][tx*4];
            b1.f = *(const float2*)&sWm[k][tx*4 + 2];
            #pragma unroll
            for (int i = 0; i < 2; i++) {
                float av = sAm[ty*2+i][k];
                u64 ap = pack2(av, av);
                ffma2(acc[i][0], ap, b0.u);
                ffma2(acc[i][1], ap, b1.u);
            }
        }
        __syncthreads();
    }

    float4 bb = *(const float4*)(bias + n0 + tx*4);
    #pragma unroll
    for (int i = 0; i < 2; i++) {
        F2 u0, u1; u0.u = acc[i][0]; u1.u = acc[i][1];
        float4 o;
        o.x = u0.f.x + bb.x; o.y = u0.f.y + bb.y;
        o.z = u1.f.x + bb.z; o.w = u1.f.y + bb.w;
        if (ELU) { o.x = elu1(o.x); o.y = elu1(o.y); o.z = elu1(o.z); o.w = elu1(o.w); }
        *(float4*)(C + (size_t)(m0 + ty*2 + i) * N + n0 + tx*4) = o;
    }
}

// ---------------- logits + mask ----------------
__global__ void logits_k(const float* __restrict__ P2, const float* __restrict__ W,
                         const float* __restrict__ bias, const int* __restrict__ mask,
                         float* __restrict__ out)
{
    int b = blockIdx.x;
    int a = threadIdx.x;
    if (a >= 19) return;
    float s = bias[a];
    const float* p = P2 + b * 256;
    #pragma unroll 8
    for (int k = 0; k < 256; k++) s += p[k] * W[k * 19 + a];
    int m = mask[b * 19 + a];
    out[b * 19 + a] = s + (m > 0 ? 0.f : -3.4028234663852886e38f);
}

// ---------------- launch ----------------
extern "C" void kernel_launch(void* const* d_in, const int* in_sizes, int n_in,
                              void* d_out, int out_size)
{
    const float* gmap  = (const float*)d_in[0];
    const int*   pos   = (const int*)  d_in[1];
    const int*   amask = (const int*)  d_in[2];
    const float* Ws    = (const float*)d_in[3];
    const float* Wn    = (const float*)d_in[4];
    const float* bs    = (const float*)d_in[5];
    const float* W_d1  = (const float*)d_in[6];
    const float* b_d1  = (const float*)d_in[7];
    const float* W_d2  = (const float*)d_in[8];
    const float* b_d2  = (const float*)d_in[9];
    const float* W_d3  = (const float*)d_in[10];
    const float* b_d3  = (const float*)d_in[11];
    const float* W_p1  = (const float*)d_in[12];
    const float* b_p1  = (const float*)d_in[13];
    const float* W_p2  = (const float*)d_in[14];
    const float* b_p2  = (const float*)d_in[15];
    const float* W_p3  = (const float*)d_in[16];
    const float* b_p3  = (const float*)d_in[17];
    float* out = (float*)d_out;

    __nv_bfloat16 *x0, *x1, *uv, *wt;
    float *ms0, *ms1, *st, *h1, *h2, *ft, *p1, *p2;
    cudaGetSymbolAddress((void**)&x0, g_xb0);
    cudaGetSymbolAddress((void**)&x1, g_xb1);
    cudaGetSymbolAddress((void**)&uv, g_uv);
    cudaGetSymbolAddress((void**)&ms0, g_ms0);
    cudaGetSymbolAddress((void**)&ms1, g_ms1);
    cudaGetSymbolAddress((void**)&wt, g_wt);
    cudaGetSymbolAddress((void**)&st, g_state);
    cudaGetSymbolAddress((void**)&h1, g_h1);
    cudaGetSymbolAddress((void**)&h2, g_h2);
    cudaGetSymbolAddress((void**)&ft, g_ft);
    cudaGetSymbolAddress((void**)&p1, g_p1);
    cudaGetSymbolAddress((void**)&p2, g_p2);

    cudaFuncSetAttribute(gnn_gemm, cudaFuncAttributeMaxDynamicSharedMemorySize, GEMM_SMEM);

    prep_wt<<<(3*256*128)/256, 256>>>(Ws, Wn, wt);

    dim3 sg(65, BATCH);
    // layer 0
    meta_agg0<<<BATCH, 1024>>>(gmap, ms0);
    gnn_gemm<<<MTOT/128, 512, GEMM_SMEM>>>(nullptr, gmap, 1, ms0, ms1, wt, bs, uv);
    gnn_stencil<<<sg, 256>>>(uv, x0, ms1);
    // layer 1
    gnn_gemm<<<MTOT/128, 512, GEMM_SMEM>>>(x0, nullptr, 0, ms1, ms0, wt + 256*128, bs + 128, uv);
    gnn_stencil<<<sg, 256>>>(uv, x1, ms0);
    // layer 2
    gnn_gemm<<<MTOT/128, 512, GEMM_SMEM>>>(x1, nullptr, 0, ms0, ms1, wt + 2*256*128, bs + 256, uv);
    gnn_stencil<<<sg, 256>>>(uv, x0, ms1);

    gather_state<<<BATCH, 128>>>(x0, pos, st);

    mlp_gemm<true><<<dim3(8, 4), 256>>>(st, W_d1, b_d1, h1, 640, 512);
    mlp_gemm<true><<<dim3(8, 4), 256>>>(h1, W_d2, b_d2, h2, 512, 512);
    mlp_gemm<true><<<dim3(4, 4), 256>>>(h2, W_d3, b_d3, ft, 512, 256);
    mlp_gemm<true><<<dim3(4, 4), 256>>>(ft, W_p1, b_p1, p1, 256, 256);
    mlp_gemm<true><<<dim3(4, 4), 256>>>(p1, W_p2, b_p2, p2, 256, 256);

    logits_k<<<BATCH, 32>>>(p2, W_p3, b_p3, amask, out);
}

// round 11
// speedup vs baseline: 1.1522x; 1.1522x over previous
#include <cuda_runtime.h>
#include <cuda_bf16.h>
#include <math.h>
#include <stdint.h>

#define BATCH 128
#define CELLS 1024
#define XROWS 1025            // cells + meta
#define GROWS 1026            // + MAgg row
#define FDIM  128
#define MTOT  (BATCH*GROWS)   // 131328

typedef unsigned long long u64;
union F2 { u64 u; float2 f; };

__device__ __forceinline__ u64 pack2(float lo, float hi){
    u64 r; asm("mov.b64 %0, {%1, %2};" : "=l"(r) : "f"(lo), "f"(hi)); return r;
}
__device__ __forceinline__ void ffma2(u64& d, u64 a, u64 b){
    asm("fma.rn.f32x2 %0, %1, %2, %0;" : "+l"(d) : "l"(a), "l"(b));
}
__device__ __forceinline__ float elu1(float v){ return v > 0.f ? v : (expf(v) - 1.f); }
__device__ __forceinline__ uint32_t smem_u32(const void* p){
    uint32_t a; asm("{ .reg .u64 t; cvta.to.shared.u64 t, %1; cvt.u32.u64 %0, t; }" : "=r"(a) : "l"(p));
    return a;
}
#define CP16(dst, src) asm volatile("cp.async.cg.shared.global [%0], [%1], 16;" :: "r"(dst), "l"(src))
#define CP_COMMIT()    asm volatile("cp.async.commit_group;")
#define CP_WAIT0()     asm volatile("cp.async.wait_group 0;" ::: "memory")

// ---------------- scratch ----------------
__device__ __nv_bfloat16 g_xb0[(size_t)BATCH*XROWS*FDIM];
__device__ __nv_bfloat16 g_xb1[(size_t)BATCH*XROWS*FDIM];
__device__ __nv_bfloat16 g_uv[(size_t)BATCH*GROWS*256];   // 0-127: u, 128-255: v
__device__ __nv_bfloat16 g_magg[BATCH*FDIM];
__device__ __nv_bfloat16 g_wt[3*256*128];
__device__ float g_state[BATCH*640];
__device__ float g_h1[BATCH*512];
__device__ float g_h2[BATCH*512];
__device__ float g_ft[BATCH*256];
__device__ float g_p1[BATCH*256];
__device__ float g_p2[BATCH*256];

// ---------------- weight prep: Wt[l][n'][k] ----------------
__global__ void prep_wt(const float* __restrict__ Ws, const float* __restrict__ Wn,
                        __nv_bfloat16* __restrict__ Wt){
    int idx = blockIdx.x * blockDim.x + threadIdx.x;
    int l = idx >> 15;
    int r = idx & 32767;
    int n = r >> 7;
    int k = r & 127;
    float v = (n < 128) ? Ws[l*16384 + k*128 + n] : Wn[l*16384 + k*128 + (n-128)];
    Wt[idx] = __float2bfloat16(v);
}

// ---------------- meta aggregation ----------------
__global__ void meta_agg(const __nv_bfloat16* __restrict__ X, const float* __restrict__ G,
                         int srcF32, __nv_bfloat16* __restrict__ MAgg){
    __shared__ float2 sm[16][64];
    int b = blockIdx.x, t = threadIdx.x;
    int f2 = t & 63, p = t >> 6;
    float2 s = make_float2(0.f, 0.f);
    int c0 = p * 64;
    if (srcF32) {
        const float2* gb = (const float2*)(G + (size_t)b * CELLS * FDIM);
        #pragma unroll 8
        for (int c = c0; c < c0 + 64; c++) {
            float2 v = gb[c*64 + f2];
            s.x += v.x; s.y += v.y;
        }
    } else {
        const __nv_bfloat162* xb = (const __nv_bfloat162*)(X + (size_t)b * XROWS * FDIM);
        #pragma unroll 8
        for (int c = c0; c < c0 + 64; c++) {
            float2 v = __bfloat1622float2(xb[c*64 + f2]);
            s.x += v.x; s.y += v.y;
        }
    }
    sm[p][f2] = s;
    __syncthreads();
    if (p == 0) {
        s = sm[0][f2];
        #pragma unroll
        for (int i = 1; i < 16; i++) { s.x += sm[i][f2].x; s.y += sm[i][f2].y; }
        ((__nv_bfloat162*)MAgg)[b*64 + f2] = __float22bfloat162_rn(s);
    }
}

// ---------------- dense GEMM: UV = A @ Wt^T (+bias on u-half) ----------------
// CTA tile 128(M) x 256(N, both halves) via two MMA passes over one shared A tile.
// 512 threads = 16 warps (4m x 4n), warp tile 32x32 per pass.
#define STR2 272
#define SMB2_OFF (128*STR2)
#define GEMM_SMEM (128*STR2 + 256*STR2)   // 104448

__device__ __forceinline__ void ldmA(uint32_t addr, uint32_t* r){
    asm volatile("ldmatrix.sync.aligned.m8n8.x4.shared.b16 {%0,%1,%2,%3}, [%4];"
        : "=r"(r[0]), "=r"(r[1]), "=r"(r[2]), "=r"(r[3]) : "r"(addr));
}

__global__ void __launch_bounds__(512, 2) gnn_gemm(
    const __nv_bfloat16* __restrict__ X, const float* __restrict__ G, int srcF32,
    const __nv_bfloat16* __restrict__ MAgg,
    const __nv_bfloat16* __restrict__ Wt, const float* __restrict__ bias,
    __nv_bfloat16* __restrict__ UV)
{
    extern __shared__ char smem[];
    uint32_t sb = smem_u32(smem);
    int t = threadIdx.x;
    int wid = t >> 5, lane = t & 31;
    int m0cta = blockIdx.x * 128;

    // ---- B tile: 256 n-rows x 128 k; thread: n = t>>1, half h = t&1 (8x16B) ----
    {
        int n = t >> 1, h = t & 1;
        const char* src = (const char*)(Wt + (size_t)n*128 + h*64);
        uint32_t dst = sb + SMB2_OFF + n*STR2 + h*128;
        #pragma unroll
        for (int j = 0; j < 8; j++) CP16(dst + j*16, src + j*16);
    }
    // ---- A tile: 128 rows x 128 k; thread: m = t>>2, quarter qh = t&3 ----
    {
        int m = t >> 2, qh = t & 3;
        int row = m0cta + m;
        int b = row / GROWS;
        int node = row - b * GROWS;
        uint32_t dst = sb + m*STR2 + qh*64;
        if (node == GROWS - 1) {
            const uint4* src = (const uint4*)(MAgg + b*FDIM + qh*32);
            #pragma unroll
            for (int j = 0; j < 4; j++) *(uint4*)(smem + m*STR2 + qh*64 + j*16) = src[j];
        } else if (!srcF32) {
            const char* src = (const char*)(X + ((size_t)b * XROWS + node) * FDIM + qh*32);
            #pragma unroll
            for (int j = 0; j < 4; j++) CP16(dst + j*16, src + j*16);
        } else {
            if (node < CELLS) {
                const float* src = G + ((size_t)b * CELLS + node) * FDIM + qh*32;
                #pragma unroll
                for (int j = 0; j < 4; j++) {
                    float4 v0 = *(const float4*)(src + j*8);
                    float4 v1 = *(const float4*)(src + j*8 + 4);
                    uint4 o;
                    __nv_bfloat162* ho = (__nv_bfloat162*)&o;
                    ho[0] = __float22bfloat162_rn(make_float2(v0.x, v0.y));
                    ho[1] = __float22bfloat162_rn(make_float2(v0.z, v0.w));
                    ho[2] = __float22bfloat162_rn(make_float2(v1.x, v1.y));
                    ho[3] = __float22bfloat162_rn(make_float2(v1.z, v1.w));
                    *(uint4*)(smem + m*STR2 + qh*64 + j*16) = o;
                }
            } else {   // meta node: x == 0 at layer 0
                uint4 z = make_uint4(0,0,0,0);
                #pragma unroll
                for (int j = 0; j < 4; j++) *(uint4*)(smem + m*STR2 + qh*64 + j*16) = z;
            }
        }
    }
    CP_COMMIT();
    CP_WAIT0();
    __syncthreads();

    // ---- MMA: two passes (u half, v half) over the same A tile ----
    int warp_m = wid >> 2;   // 0-3
    int warp_n = wid & 3;    // 0-3
    uint32_t saA = sb + (warp_m*32 + (lane & 15))*STR2 + (lane >> 4)*16;
    int gr = lane >> 2, gc = lane & 3;

    #pragma unroll
    for (int nhalf = 0; nhalf < 2; nhalf++) {
        uint32_t saB = sb + SMB2_OFF
                     + (nhalf*128 + warp_n*32 + (lane >> 4)*8 + (lane & 7))*STR2
                     + ((lane >> 3) & 1)*16;

        float acc[2][4][4];
        #pragma unroll
        for (int i = 0; i < 2; i++)
            #pragma unroll
            for (int j = 0; j < 4; j++)
                #pragma unroll
                for (int q = 0; q < 4; q++) acc[i][j][q] = 0.f;

        #pragma unroll
        for (int ks = 0; ks < 8; ks++) {
            uint32_t ko = ks * 32;
            uint32_t a0[4], a1[4], b0[4], b1[4];
            ldmA(saA + ko, a0);
            ldmA(saA + 16*STR2 + ko, a1);
            ldmA(saB + ko, b0);
            ldmA(saB + 16*STR2 + ko, b1);
            uint32_t* afr[2] = { a0, a1 };
            uint32_t* bfr[2] = { b0, b1 };
            #pragma unroll
            for (int mf = 0; mf < 2; mf++)
                #pragma unroll
                for (int nf = 0; nf < 4; nf++) {
                    uint32_t rb0 = bfr[nf >> 1][(nf & 1)*2];
                    uint32_t rb1 = bfr[nf >> 1][(nf & 1)*2 + 1];
                    asm volatile("mma.sync.aligned.m16n8k16.row.col.f32.bf16.bf16.f32 "
                        "{%0,%1,%2,%3}, {%4,%5,%6,%7}, {%8,%9}, {%0,%1,%2,%3};"
                        : "+f"(acc[mf][nf][0]), "+f"(acc[mf][nf][1]),
                          "+f"(acc[mf][nf][2]), "+f"(acc[mf][nf][3])
                        : "r"(afr[mf][0]), "r"(afr[mf][1]), "r"(afr[mf][2]), "r"(afr[mf][3]),
                          "r"(rb0), "r"(rb1));
                }
        }

        // epilogue for this half
        #pragma unroll
        for (int nf = 0; nf < 4; nf++) {
            int coln = warp_n*32 + nf*8 + 2*gc;
            float2 bb = make_float2(0.f, 0.f);
            if (nhalf == 0) bb = *(const float2*)(bias + coln);
            int colg = nhalf*128 + coln;
            #pragma unroll
            for (int mf = 0; mf < 2; mf++) {
                size_t r0 = (size_t)m0cta + warp_m*32 + mf*16 + gr;
                float v0 = acc[mf][nf][0] + bb.x;
                float v1 = acc[mf][nf][1] + bb.y;
                float v2 = acc[mf][nf][2] + bb.x;
                float v3 = acc[mf][nf][3] + bb.y;
                *(__nv_bfloat162*)(UV + r0 * 256 + colg)       = __float22bfloat162_rn(make_float2(v0, v1));
                *(__nv_bfloat162*)(UV + (r0 + 8) * 256 + colg) = __float22bfloat162_rn(make_float2(v2, v3));
            }
        }
    }
}

// ---------------- stencil: y = elu(u + v[meta] + sum v[nbrs]), bf16 adds ----------------
__device__ __forceinline__ void badd8(const __nv_bfloat16* p, __nv_bfloat162* s){
    uint4 v = *(const uint4*)p;
    __nv_bfloat162* h = (__nv_bfloat162*)&v;
    #pragma unroll
    for (int i = 0; i < 4; i++) s[i] = __hadd2(s[i], h[i]);
}

__global__ void gnn_stencil(const __nv_bfloat16* __restrict__ UV, __nv_bfloat16* __restrict__ Y){
    int idx = blockIdx.x * blockDim.x + threadIdx.x;   // BATCH*XROWS*16
    int q = idx & 15;
    int nb = idx >> 4;
    int node = nb % XROWS;
    int b = nb / XROWS;
    const __nv_bfloat16* uvb = UV + (size_t)b * GROWS * 256;
    int qo = q * 8;

    __nv_bfloat162 s[4];
    {   // u
        uint4 v = *(const uint4*)(uvb + (size_t)node*256 + qo);
        __nv_bfloat162* h = (__nv_bfloat162*)&v;
        #pragma unroll
        for (int i = 0; i < 4; i++) s[i] = h[i];
    }
    const __nv_bfloat16* vb = uvb + 128 + qo;
    if (node < CELLS) {
        badd8(vb + (size_t)CELLS*256, s);       // v[meta]
        int r = node >> 5, c = node & 31;
        if (r > 0)  badd8(vb + (size_t)(node-32)*256, s);
        if (r < 31) badd8(vb + (size_t)(node+32)*256, s);
        if (c > 0)  badd8(vb + (size_t)(node-1)*256, s);
        if (c < 31) badd8(vb + (size_t)(node+1)*256, s);
    } else {
        badd8(vb + (size_t)(CELLS+1)*256, s);   // v[MAgg row]
    }
    uint4 o;
    __nv_bfloat162* ho = (__nv_bfloat162*)&o;
    #pragma unroll
    for (int i = 0; i < 4; i++) {
        float2 f = __bfloat1622float2(s[i]);
        ho[i] = __float22bfloat162_rn(make_float2(elu1(f.x), elu1(f.y)));
    }
    *(uint4*)(Y + ((size_t)b * XROWS + node) * FDIM + qo) = o;
}

// ---------------- gather 5 cells ----------------
__global__ void gather_state(const __nv_bfloat16* __restrict__ X, const int* __restrict__ pos,
                             float* __restrict__ state)
{
    int b = blockIdx.x;
    int f = threadIdx.x;
    int r = pos[2*b + 0];
    int c = pos[2*b + 1];
    const int dr[5] = {-1, 0, 1, 0, 0};
    const int dc[5] = { 0,-1, 0, 1, 0};
    #pragma unroll
    for (int o = 0; o < 5; o++) {
        int j  = (r + dr[o] + 1) * 32 + (c + dc[o] + 1);
        int jr = j / 34, jc = j % 34;
        float v = 0.f;
        if (jr >= 1 && jr <= 32 && jc >= 1 && jc <= 32) {
            int cell = (jr - 1) * 32 + (jc - 1);
            v = __bfloat162float(X[((size_t)b * XROWS + cell) * FDIM + f]);
        }
        state[b * 640 + o * FDIM + f] = v;
    }
}

// ---------------- small MLP GEMM (fp32, f32x2), tile 64x64, BK=32 ----------------
template<bool ELU>
__global__ void __launch_bounds__(256) mlp_gemm(
    const float* __restrict__ A, const float* __restrict__ W,
    const float* __restrict__ bias, float* __restrict__ C, int K, int N)
{
    __shared__ float sAm[64][36];
    __shared__ float sWm[32][64];
    int t = threadIdx.x;
    int tx = t & 15;
    int ty = t >> 4;
    int m0 = blockIdx.y * 64;
    int n0 = blockIdx.x * 64;

    u64 acc[4][2];
    #pragma unroll
    for (int i = 0; i < 4; i++) { acc[i][0] = 0ULL; acc[i][1] = 0ULL; }

    int arow = t >> 2, acg = t & 3;
    int wr = t >> 4, wn = (t & 15) * 4;

    for (int kk = 0; kk < K; kk += 32) {
        #pragma unroll
        for (int kh = 0; kh < 2; kh++)
            *(float4*)&sAm[arow][kh*16 + acg*4] =
                *(const float4*)(A + (size_t)(m0 + arow) * K + kk + kh*16 + acg*4);
        #pragma unroll
        for (int rh = 0; rh < 2; rh++)
            *(float4*)&sWm[wr + rh*16][wn] =
                *(const float4*)(W + (size_t)(kk + wr + rh*16) * N + n0 + wn);
        __syncthreads();
        #pragma unroll
        for (int k = 0; k < 32; k++) {
            F2 b0, b1;
            b0.f = *(const float2*)&sWm[k][tx*4];
            b1.f = *(const float2*)&sWm[k][tx*4 + 2];
            #pragma unroll
            for (int i = 0; i < 4; i++) {
                float av = sAm[ty*4+i][k];
                u64 ap = pack2(av, av);
                ffma2(acc[i][0], ap, b0.u);
                ffma2(acc[i][1], ap, b1.u);
            }
        }
        __syncthreads();
    }

    float4 bb = *(const float4*)(bias + n0 + tx*4);
    #pragma unroll
    for (int i = 0; i < 4; i++) {
        F2 u0, u1; u0.u = acc[i][0]; u1.u = acc[i][1];
        float4 o;
        o.x = u0.f.x + bb.x; o.y = u0.f.y + bb.y;
        o.z = u1.f.x + bb.z; o.w = u1.f.y + bb.w;
        if (ELU) { o.x = elu1(o.x); o.y = elu1(o.y); o.z = elu1(o.z); o.w = elu1(o.w); }
        *(float4*)(C + (size_t)(m0 + ty*4 + i) * N + n0 + tx*4) = o;
    }
}

// ---------------- logits + mask ----------------
__global__ void logits_k(const float* __restrict__ P2, const float* __restrict__ W,
                         const float* __restrict__ bias, const int* __restrict__ mask,
                         float* __restrict__ out)
{
    int b = blockIdx.x;
    int a = threadIdx.x;
    if (a >= 19) return;
    float s = bias[a];
    const float* p = P2 + b * 256;
    #pragma unroll 8
    for (int k = 0; k < 256; k++) s += p[k] * W[k * 19 + a];
    int m = mask[b * 19 + a];
    out[b * 19 + a] = s + (m > 0 ? 0.f : -3.4028234663852886e38f);
}

// ---------------- launch ----------------
extern "C" void kernel_launch(void* const* d_in, const int* in_sizes, int n_in,
                              void* d_out, int out_size)
{
    const float* gmap  = (const float*)d_in[0];
    const int*   pos   = (const int*)  d_in[1];
    const int*   amask = (const int*)  d_in[2];
    const float* Ws    = (const float*)d_in[3];
    const float* Wn    = (const float*)d_in[4];
    const float* bs    = (const float*)d_in[5];
    const float* W_d1  = (const float*)d_in[6];
    const float* b_d1  = (const float*)d_in[7];
    const float* W_d2  = (const float*)d_in[8];
    const float* b_d2  = (const float*)d_in[9];
    const float* W_d3  = (const float*)d_in[10];
    const float* b_d3  = (const float*)d_in[11];
    const float* W_p1  = (const float*)d_in[12];
    const float* b_p1  = (const float*)d_in[13];
    const float* W_p2  = (const float*)d_in[14];
    const float* b_p2  = (const float*)d_in[15];
    const float* W_p3  = (const float*)d_in[16];
    const float* b_p3  = (const float*)d_in[17];
    float* out = (float*)d_out;

    __nv_bfloat16 *x0, *x1, *uv, *ma, *wt;
    float *st, *h1, *h2, *ft, *p1, *p2;
    cudaGetSymbolAddress((void**)&x0, g_xb0);
    cudaGetSymbolAddress((void**)&x1, g_xb1);
    cudaGetSymbolAddress((void**)&uv, g_uv);
    cudaGetSymbolAddress((void**)&ma, g_magg);
    cudaGetSymbolAddress((void**)&wt, g_wt);
    cudaGetSymbolAddress((void**)&st, g_state);
    cudaGetSymbolAddress((void**)&h1, g_h1);
    cudaGetSymbolAddress((void**)&h2, g_h2);
    cudaGetSymbolAddress((void**)&ft, g_ft);
    cudaGetSymbolAddress((void**)&p1, g_p1);
    cudaGetSymbolAddress((void**)&p2, g_p2);

    cudaFuncSetAttribute(gnn_gemm, cudaFuncAttributeMaxDynamicSharedMemorySize, GEMM_SMEM);

    prep_wt<<<(3*256*128)/256, 256>>>(Ws, Wn, wt);

    // layer 0 (A from gmap fp32)
    meta_agg<<<BATCH, 1024>>>(nullptr, gmap, 1, ma);
    gnn_gemm<<<MTOT/128, 512, GEMM_SMEM>>>(nullptr, gmap, 1, ma, wt, bs, uv);
    gnn_stencil<<<(BATCH*XROWS*16)/256, 256>>>(uv, x0);
    // layer 1
    meta_agg<<<BATCH, 1024>>>(x0, nullptr, 0, ma);
    gnn_gemm<<<MTOT/128, 512, GEMM_SMEM>>>(x0, nullptr, 0, ma, wt + 256*128, bs + 128, uv);
    gnn_stencil<<<(BATCH*XROWS*16)/256, 256>>>(uv, x1);
    // layer 2
    meta_agg<<<BATCH, 1024>>>(x1, nullptr, 0, ma);
    gnn_gemm<<<MTOT/128, 512, GEMM_SMEM>>>(x1, nullptr, 0, ma, wt + 2*256*128, bs + 256, uv);
    gnn_stencil<<<(BATCH*XROWS*16)/256, 256>>>(uv, x0);

    gather_state<<<BATCH, 128>>>(x0, pos, st);

    mlp_gemm<true><<<dim3(8, 2), 256>>>(st, W_d1, b_d1, h1, 640, 512);
    mlp_gemm<true><<<dim3(8, 2), 256>>>(h1, W_d2, b_d2, h2, 512, 512);
    mlp_gemm<true><<<dim3(4, 2), 256>>>(h2, W_d3, b_d3, ft, 512, 256);
    mlp_gemm<true><<<dim3(4, 2), 256>>>(ft, W_p1, b_p1, p1, 256, 256);
    mlp_gemm<true><<<dim3(4, 2), 256>>>(p1, W_p2, b_p2, p2, 256, 256);

    logits_k<<<BATCH, 32>>>(p2, W_p3, b_p3, amask, out);
}

// round 12
// speedup vs baseline: 1.5725x; 1.3647x over previous
#include <cuda_runtime.h>
#include <cuda_bf16.h>
#include <math.h>
#include <stdint.h>

#define BATCH 128
#define CELLS 1024
#define XROWS 1025            // cells + meta
#define GROWS 1026            // + MAgg row
#define FDIM  128
#define MTOT  (BATCH*GROWS)   // 131328

typedef unsigned long long u64;
union F2 { u64 u; float2 f; };

__device__ __forceinline__ u64 pack2(float lo, float hi){
    u64 r; asm("mov.b64 %0, {%1, %2};" : "=l"(r) : "f"(lo), "f"(hi)); return r;
}
__device__ __forceinline__ void ffma2(u64& d, u64 a, u64 b){
    asm("fma.rn.f32x2 %0, %1, %2, %0;" : "+l"(d) : "l"(a), "l"(b));
}
__device__ __forceinline__ float elu1(float v){ return v > 0.f ? v : (expf(v) - 1.f); }
__device__ __forceinline__ uint32_t smem_u32(const void* p){
    uint32_t a; asm("{ .reg .u64 t; cvta.to.shared.u64 t, %1; cvt.u32.u64 %0, t; }" : "=r"(a) : "l"(p));
    return a;
}
#define CP16(dst, src) asm volatile("cp.async.cg.shared.global [%0], [%1], 16;" :: "r"(dst), "l"(src))
#define CP_COMMIT()    asm volatile("cp.async.commit_group;")
#define CP_WAIT0()     asm volatile("cp.async.wait_group 0;" ::: "memory")

// ---------------- scratch ----------------
__device__ __nv_bfloat16 g_xb0[(size_t)BATCH*XROWS*FDIM];
__device__ __nv_bfloat16 g_xb1[(size_t)BATCH*XROWS*FDIM];
__device__ __nv_bfloat16 g_uv[(size_t)BATCH*GROWS*256];   // 0-127: u, 128-255: v
__device__ __nv_bfloat16 g_magg[BATCH*FDIM];
__device__ __nv_bfloat16 g_wt[3*256*128];   // [l][n'=256][k=128]: n'<128 Ws^T, else Wn^T
__device__ float g_state[BATCH*640];
__device__ float g_h1[BATCH*512];
__device__ float g_h2[BATCH*512];
__device__ float g_ft[BATCH*256];
__device__ float g_p1[BATCH*256];
__device__ float g_p2[BATCH*256];

// ---------------- weight prep: Wt[l][n'][k] ----------------
__global__ void prep_wt(const float* __restrict__ Ws, const float* __restrict__ Wn,
                        __nv_bfloat16* __restrict__ Wt){
    int idx = blockIdx.x * blockDim.x + threadIdx.x;
    int l = idx >> 15;
    int r = idx & 32767;
    int n = r >> 7;
    int k = r & 127;
    float v = (n < 128) ? Ws[l*16384 + k*128 + n] : Wn[l*16384 + k*128 + (n-128)];
    Wt[idx] = __float2bfloat16(v);
}

// ---------------- meta aggregation ----------------
__global__ void meta_agg(const __nv_bfloat16* __restrict__ X, const float* __restrict__ G,
                         int srcF32, __nv_bfloat16* __restrict__ MAgg){
    __shared__ float2 sm[16][64];
    int b = blockIdx.x, t = threadIdx.x;
    int f2 = t & 63, p = t >> 6;
    float2 s = make_float2(0.f, 0.f);
    int c0 = p * 64;
    if (srcF32) {
        const float2* gb = (const float2*)(G + (size_t)b * CELLS * FDIM);
        #pragma unroll 8
        for (int c = c0; c < c0 + 64; c++) {
            float2 v = gb[c*64 + f2];
            s.x += v.x; s.y += v.y;
        }
    } else {
        const __nv_bfloat162* xb = (const __nv_bfloat162*)(X + (size_t)b * XROWS * FDIM);
        #pragma unroll 8
        for (int c = c0; c < c0 + 64; c++) {
            float2 v = __bfloat1622float2(xb[c*64 + f2]);
            s.x += v.x; s.y += v.y;
        }
    }
    sm[p][f2] = s;
    __syncthreads();
    if (p == 0) {
        s = sm[0][f2];
        #pragma unroll
        for (int i = 1; i < 16; i++) { s.x += sm[i][f2].x; s.y += sm[i][f2].y; }
        ((__nv_bfloat162*)MAgg)[b*64 + f2] = __float22bfloat162_rn(s);
    }
}

// ---------------- dense GEMM: UV = A @ Wt^T (+bias on u-half) ----------------
// CTA tile 128x128, K=128. 512 threads = 16 warps (4m x 4n), warp 32x32.
// grid (1026, 2): y = N-half. 2 CTAs/SM (69632B smem).
#define STR2 272
#define SMB2_OFF (128*STR2)
#define GEMM_SMEM (256*STR2)   // 69632

__device__ __forceinline__ void ldmA(uint32_t addr, uint32_t* r){
    asm volatile("ldmatrix.sync.aligned.m8n8.x4.shared.b16 {%0,%1,%2,%3}, [%4];"
        : "=r"(r[0]), "=r"(r[1]), "=r"(r[2]), "=r"(r[3]) : "r"(addr));
}

__global__ void __launch_bounds__(512, 2) gnn_gemm(
    const __nv_bfloat16* __restrict__ X, const float* __restrict__ G, int srcF32,
    const __nv_bfloat16* __restrict__ MAgg,
    const __nv_bfloat16* __restrict__ Wt, const float* __restrict__ bias,
    __nv_bfloat16* __restrict__ UV)
{
    extern __shared__ char smem[];
    uint32_t sb = smem_u32(smem);
    int t = threadIdx.x;
    int wid = t >> 5, lane = t & 31;
    int m0cta = blockIdx.x * 128;
    int nhalf = blockIdx.y;

    // ---- B tile: 128 n-rows x 128 k; thread: n = t>>2, quarter qh = t&3 (4x16B) ----
    {
        int n = t >> 2, qh = t & 3;
        const char* src = (const char*)(Wt + ((size_t)(nhalf*128 + n))*128 + qh*32);
        uint32_t dst = sb + SMB2_OFF + n*STR2 + qh*64;
        #pragma unroll
        for (int j = 0; j < 4; j++) CP16(dst + j*16, src + j*16);
    }
    // ---- A tile: 128 rows x 128 k; thread: m = t>>2, quarter qh = t&3 ----
    {
        int m = t >> 2, qh = t & 3;
        int row = m0cta + m;
        int b = row / GROWS;
        int node = row - b * GROWS;
        uint32_t dst = sb + m*STR2 + qh*64;
        if (node == GROWS - 1) {
            const uint4* src = (const uint4*)(MAgg + b*FDIM + qh*32);
            #pragma unroll
            for (int j = 0; j < 4; j++) *(uint4*)(smem + m*STR2 + qh*64 + j*16) = src[j];
        } else if (!srcF32) {
            const char* src = (const char*)(X + ((size_t)b * XROWS + node) * FDIM + qh*32);
            #pragma unroll
            for (int j = 0; j < 4; j++) CP16(dst + j*16, src + j*16);
        } else {
            if (node < CELLS) {
                const float* src = G + ((size_t)b * CELLS + node) * FDIM + qh*32;
                #pragma unroll
                for (int j = 0; j < 4; j++) {
                    float4 v0 = *(const float4*)(src + j*8);
                    float4 v1 = *(const float4*)(src + j*8 + 4);
                    uint4 o;
                    __nv_bfloat162* ho = (__nv_bfloat162*)&o;
                    ho[0] = __float22bfloat162_rn(make_float2(v0.x, v0.y));
                    ho[1] = __float22bfloat162_rn(make_float2(v0.z, v0.w));
                    ho[2] = __float22bfloat162_rn(make_float2(v1.x, v1.y));
                    ho[3] = __float22bfloat162_rn(make_float2(v1.z, v1.w));
                    *(uint4*)(smem + m*STR2 + qh*64 + j*16) = o;
                }
            } else {   // meta node: x == 0 at layer 0
                uint4 z = make_uint4(0,0,0,0);
                #pragma unroll
                for (int j = 0; j < 4; j++) *(uint4*)(smem + m*STR2 + qh*64 + j*16) = z;
            }
        }
    }
    CP_COMMIT();
    CP_WAIT0();
    __syncthreads();

    // ---- MMA: 16 warps, warp tile 32x32, single-buffer frags ----
    int warp_m = wid >> 2;   // 0-3
    int warp_n = wid & 3;    // 0-3
    uint32_t saA = sb + (warp_m*32 + (lane & 15))*STR2 + (lane >> 4)*16;
    uint32_t saB = sb + SMB2_OFF + (warp_n*32 + (lane >> 4)*8 + (lane & 7))*STR2 + ((lane >> 3) & 1)*16;

    float acc[2][4][4];
    #pragma unroll
    for (int i = 0; i < 2; i++)
        #pragma unroll
        for (int j = 0; j < 4; j++)
            #pragma unroll
            for (int q = 0; q < 4; q++) acc[i][j][q] = 0.f;

    #pragma unroll
    for (int ks = 0; ks < 8; ks++) {
        uint32_t ko = ks * 32;
        uint32_t a0[4], a1[4], b0[4], b1[4];   // b0: nf 0,1 ; b1: nf 2,3
        ldmA(saA + ko, a0);
        ldmA(saA + 16*STR2 + ko, a1);
        ldmA(saB + ko, b0);
        ldmA(saB + 16*STR2 + ko, b1);
        uint32_t* afr[2] = { a0, a1 };
        uint32_t* bfr[2] = { b0, b1 };
        #pragma unroll
        for (int mf = 0; mf < 2; mf++)
            #pragma unroll
            for (int nf = 0; nf < 4; nf++) {
                uint32_t rb0 = bfr[nf >> 1][(nf & 1)*2];
                uint32_t rb1 = bfr[nf >> 1][(nf & 1)*2 + 1];
                asm volatile("mma.sync.aligned.m16n8k16.row.col.f32.bf16.bf16.f32 "
                    "{%0,%1,%2,%3}, {%4,%5,%6,%7}, {%8,%9}, {%0,%1,%2,%3};"
                    : "+f"(acc[mf][nf][0]), "+f"(acc[mf][nf][1]),
                      "+f"(acc[mf][nf][2]), "+f"(acc[mf][nf][3])
                    : "r"(afr[mf][0]), "r"(afr[mf][1]), "r"(afr[mf][2]), "r"(afr[mf][3]),
                      "r"(rb0), "r"(rb1));
            }
    }

    // ---- epilogue ----
    int gr = lane >> 2, gc = lane & 3;
    #pragma unroll
    for (int nf = 0; nf < 4; nf++) {
        int coln = warp_n*32 + nf*8 + 2*gc;
        float2 bb = make_float2(0.f, 0.f);
        if (nhalf == 0) bb = *(const float2*)(bias + coln);
        int colg = nhalf*128 + coln;
        #pragma unroll
        for (int mf = 0; mf < 2; mf++) {
            size_t r0 = (size_t)m0cta + warp_m*32 + mf*16 + gr;
            float v0 = acc[mf][nf][0] + bb.x;
            float v1 = acc[mf][nf][1] + bb.y;
            float v2 = acc[mf][nf][2] + bb.x;
            float v3 = acc[mf][nf][3] + bb.y;
            *(__nv_bfloat162*)(UV + r0 * 256 + colg)       = __float22bfloat162_rn(make_float2(v0, v1));
            *(__nv_bfloat162*)(UV + (r0 + 8) * 256 + colg) = __float22bfloat162_rn(make_float2(v2, v3));
        }
    }
}

// ---------------- stencil: y = elu(u + v[meta] + sum v[nbrs]), bf16 adds ----------------
__device__ __forceinline__ void badd8(const __nv_bfloat16* p, __nv_bfloat162* s){
    uint4 v = *(const uint4*)p;
    __nv_bfloat162* h = (__nv_bfloat162*)&v;
    #pragma unroll
    for (int i = 0; i < 4; i++) s[i] = __hadd2(s[i], h[i]);
}

__global__ void gnn_stencil(const __nv_bfloat16* __restrict__ UV, __nv_bfloat16* __restrict__ Y){
    int idx = blockIdx.x * blockDim.x + threadIdx.x;   // BATCH*XROWS*16
    int q = idx & 15;
    int nb = idx >> 4;
    int node = nb % XROWS;
    int b = nb / XROWS;
    const __nv_bfloat16* uvb = UV + (size_t)b * GROWS * 256;
    int qo = q * 8;

    __nv_bfloat162 s[4];
    {   // u
        uint4 v = *(const uint4*)(uvb + (size_t)node*256 + qo);
        __nv_bfloat162* h = (__nv_bfloat162*)&v;
        #pragma unroll
        for (int i = 0; i < 4; i++) s[i] = h[i];
    }
    const __nv_bfloat16* vb = uvb + 128 + qo;
    if (node < CELLS) {
        badd8(vb + (size_t)CELLS*256, s);       // v[meta]
        int r = node >> 5, c = node & 31;
        if (r > 0)  badd8(vb + (size_t)(node-32)*256, s);
        if (r < 31) badd8(vb + (size_t)(node+32)*256, s);
        if (c > 0)  badd8(vb + (size_t)(node-1)*256, s);
        if (c < 31) badd8(vb + (size_t)(node+1)*256, s);
    } else {
        badd8(vb + (size_t)(CELLS+1)*256, s);   // v[MAgg row]
    }
    uint4 o;
    __nv_bfloat162* ho = (__nv_bfloat162*)&o;
    #pragma unroll
    for (int i = 0; i < 4; i++) {
        float2 f = __bfloat1622float2(s[i]);
        ho[i] = __float22bfloat162_rn(make_float2(elu1(f.x), elu1(f.y)));
    }
    *(uint4*)(Y + ((size_t)b * XROWS + node) * FDIM + qo) = o;
}

// ---------------- gather 5 cells ----------------
__global__ void gather_state(const __nv_bfloat16* __restrict__ X, const int* __restrict__ pos,
                             float* __restrict__ state)
{
    int b = blockIdx.x;
    int f = threadIdx.x;
    int r = pos[2*b + 0];
    int c = pos[2*b + 1];
    const int dr[5] = {-1, 0, 1, 0, 0};
    const int dc[5] = { 0,-1, 0, 1, 0};
    #pragma unroll
    for (int o = 0; o < 5; o++) {
        int j  = (r + dr[o] + 1) * 32 + (c + dc[o] + 1);
        int jr = j / 34, jc = j % 34;
        float v = 0.f;
        if (jr >= 1 && jr <= 32 && jc >= 1 && jc <= 32) {
            int cell = (jr - 1) * 32 + (jc - 1);
            v = __bfloat162float(X[((size_t)b * XROWS + cell) * FDIM + f]);
        }
        state[b * 640 + o * FDIM + f] = v;
    }
}

// ---------------- small MLP GEMM (fp32, f32x2), tile 32x64 ----------------
template<bool ELU>
__global__ void __launch_bounds__(256) mlp_gemm(
    const float* __restrict__ A, const float* __restrict__ W,
    const float* __restrict__ bias, float* __restrict__ C, int K, int N)
{
    __shared__ float sAm[32][36];
    __shared__ float sWm[32][68];
    int t = threadIdx.x;
    int tx = t & 15;          // cols tx*4
    int ty = t >> 4;          // rows ty*2, ty*2+1
    int m0 = blockIdx.y * 32;
    int n0 = blockIdx.x * 64;

    u64 acc[2][2];
    acc[0][0] = acc[0][1] = acc[1][0] = acc[1][1] = 0ULL;

    int arow = t >> 3, acg = t & 7;
    int wr = t >> 4, wn = (t & 15) * 4;

    for (int kk = 0; kk < K; kk += 32) {
        *(float4*)&sAm[arow][acg*4] = *(const float4*)(A + (size_t)(m0 + arow) * K + kk + acg*4);
        *(float4*)&sWm[wr][wn]      = *(const float4*)(W + (size_t)(kk + wr) * N + n0 + wn);
        *(float4*)&sWm[wr+16][wn]   = *(const float4*)(W + (size_t)(kk + wr + 16) * N + n0 + wn);
        __syncthreads();
        #pragma unroll
        for (int k = 0; k < 32; k++) {
            F2 b0, b1;
            b0.f = *(const float2*)&sWm[k][tx*4];
            b1.f = *(const float2*)&sWm[k][tx*4 + 2];
            #pragma unroll
            for (int i = 0; i < 2; i++) {
                float av = sAm[ty*2+i][k];
                u64 ap = pack2(av, av);
                ffma2(acc[i][0], ap, b0.u);
                ffma2(acc[i][1], ap, b1.u);
            }
        }
        __syncthreads();
    }

    float4 bb = *(const float4*)(bias + n0 + tx*4);
    #pragma unroll
    for (int i = 0; i < 2; i++) {
        F2 u0, u1; u0.u = acc[i][0]; u1.u = acc[i][1];
        float4 o;
        o.x = u0.f.x + bb.x; o.y = u0.f.y + bb.y;
        o.z = u1.f.x + bb.z; o.w = u1.f.y + bb.w;
        if (ELU) { o.x = elu1(o.x); o.y = elu1(o.y); o.z = elu1(o.z); o.w = elu1(o.w); }
        *(float4*)(C + (size_t)(m0 + ty*2 + i) * N + n0 + tx*4) = o;
    }
}

// ---------------- logits + mask ----------------
__global__ void logits_k(const float* __restrict__ P2, const float* __restrict__ W,
                         const float* __restrict__ bias, const int* __restrict__ mask,
                         float* __restrict__ out)
{
    int b = blockIdx.x;
    int a = threadIdx.x;
    if (a >= 19) return;
    float s = bias[a];
    const float* p = P2 + b * 256;
    #pragma unroll 8
    for (int k = 0; k < 256; k++) s += p[k] * W[k * 19 + a];
    int m = mask[b * 19 + a];
    out[b * 19 + a] = s + (m > 0 ? 0.f : -3.4028234663852886e38f);
}

// ---------------- launch ----------------
extern "C" void kernel_launch(void* const* d_in, const int* in_sizes, int n_in,
                              void* d_out, int out_size)
{
    const float* gmap  = (const float*)d_in[0];
    const int*   pos   = (const int*)  d_in[1];
    const int*   amask = (const int*)  d_in[2];
    const float* Ws    = (const float*)d_in[3];
    const float* Wn    = (const float*)d_in[4];
    const float* bs    = (const float*)d_in[5];
    const float* W_d1  = (const float*)d_in[6];
    const float* b_d1  = (const float*)d_in[7];
    const float* W_d2  = (const float*)d_in[8];
    const float* b_d2  = (const float*)d_in[9];
    const float* W_d3  = (const float*)d_in[10];
    const float* b_d3  = (const float*)d_in[11];
    const float* W_p1  = (const float*)d_in[12];
    const float* b_p1  = (const float*)d_in[13];
    const float* W_p2  = (const float*)d_in[14];
    const float* b_p2  = (const float*)d_in[15];
    const float* W_p3  = (const float*)d_in[16];
    const float* b_p3  = (const float*)d_in[17];
    float* out = (float*)d_out;

    __nv_bfloat16 *x0, *x1, *uv, *ma, *wt;
    float *st, *h1, *h2, *ft, *p1, *p2;
    cudaGetSymbolAddress((void**)&x0, g_xb0);
    cudaGetSymbolAddress((void**)&x1, g_xb1);
    cudaGetSymbolAddress((void**)&uv, g_uv);
    cudaGetSymbolAddress((void**)&ma, g_magg);
    cudaGetSymbolAddress((void**)&wt, g_wt);
    cudaGetSymbolAddress((void**)&st, g_state);
    cudaGetSymbolAddress((void**)&h1, g_h1);
    cudaGetSymbolAddress((void**)&h2, g_h2);
    cudaGetSymbolAddress((void**)&ft, g_ft);
    cudaGetSymbolAddress((void**)&p1, g_p1);
    cudaGetSymbolAddress((void**)&p2, g_p2);

    cudaFuncSetAttribute(gnn_gemm, cudaFuncAttributeMaxDynamicSharedMemorySize, GEMM_SMEM);

    prep_wt<<<(3*256*128)/256, 256>>>(Ws, Wn, wt);

    dim3 gg(MTOT/128, 2);
    // layer 0 (A from gmap fp32)
    meta_agg<<<BATCH, 1024>>>(nullptr, gmap, 1, ma);
    gnn_gemm<<<gg, 512, GEMM_SMEM>>>(nullptr, gmap, 1, ma, wt, bs, uv);
    gnn_stencil<<<(BATCH*XROWS*16)/256, 256>>>(uv, x0);
    // layer 1
    meta_agg<<<BATCH, 1024>>>(x0, nullptr, 0, ma);
    gnn_gemm<<<gg, 512, GEMM_SMEM>>>(x0, nullptr, 0, ma, wt + 256*128, bs + 128, uv);
    gnn_stencil<<<(BATCH*XROWS*16)/256, 256>>>(uv, x1);
    // layer 2
    meta_agg<<<BATCH, 1024>>>(x1, nullptr, 0, ma);
    gnn_gemm<<<gg, 512, GEMM_SMEM>>>(x1, nullptr, 0, ma, wt + 2*256*128, bs + 256, uv);
    gnn_stencil<<<(BATCH*XROWS*16)/256, 256>>>(uv, x0);

    gather_state<<<BATCH, 128>>>(x0, pos, st);

    mlp_gemm<true><<<dim3(8, 4), 256>>>(st, W_d1, b_d1, h1, 640, 512);
    mlp_gemm<true><<<dim3(8, 4), 256>>>(h1, W_d2, b_d2, h2, 512, 512);
    mlp_gemm<true><<<dim3(4, 4), 256>>>(h2, W_d3, b_d3, ft, 512, 256);
    mlp_gemm<true><<<dim3(4, 4), 256>>>(ft, W_p1, b_p1, p1, 256, 256);
    mlp_gemm<true><<<dim3(4, 4), 256>>>(p1, W_p2, b_p2, p2, 256, 256);

    logits_k<<<BATCH, 32>>>(p2, W_p3, b_p3, amask, out);
}

// round 13
// speedup vs baseline: 1.7695x; 1.1253x over previous
#include <cuda_runtime.h>
#include <cuda_bf16.h>
#include <math.h>
#include <stdint.h>

#define BATCH 128
#define CELLS 1024
#define XROWS 1025            // cells + meta
#define GROWS 1026            // + MAgg row
#define FDIM  128
#define MTOT  (BATCH*GROWS)   // 131328

typedef unsigned long long u64;
union F2 { u64 u; float2 f; };

__device__ __forceinline__ u64 pack2(float lo, float hi){
    u64 r; asm("mov.b64 %0, {%1, %2};" : "=l"(r) : "f"(lo), "f"(hi)); return r;
}
__device__ __forceinline__ void ffma2(u64& d, u64 a, u64 b){
    asm("fma.rn.f32x2 %0, %1, %2, %0;" : "+l"(d) : "l"(a), "l"(b));
}
__device__ __forceinline__ float elu1(float v){ return v > 0.f ? v : (expf(v) - 1.f); }
__device__ __forceinline__ uint32_t smem_u32(const void* p){
    uint32_t a; asm("{ .reg .u64 t; cvta.to.shared.u64 t, %1; cvt.u32.u64 %0, t; }" : "=r"(a) : "l"(p));
    return a;
}
#define CP16(dst, src) asm volatile("cp.async.cg.shared.global [%0], [%1], 16;" :: "r"(dst), "l"(src))
#define CP_COMMIT()    asm volatile("cp.async.commit_group;")
#define CP_WAIT(n)     asm volatile("cp.async.wait_group %0;" :: "n"(n) : "memory")

// ---------------- scratch ----------------
__device__ __nv_bfloat16 g_xb0[(size_t)BATCH*XROWS*FDIM];
__device__ __nv_bfloat16 g_xb1[(size_t)BATCH*XROWS*FDIM];
__device__ __nv_bfloat16 g_uv[(size_t)BATCH*GROWS*256];   // 0-127: u, 128-255: v
__device__ __nv_bfloat16 g_magg[BATCH*FDIM];
__device__ __nv_bfloat16 g_wt[3*256*128];   // [l][n'=256][k=128]
__device__ float g_state[BATCH*640];
__device__ float g_h1[BATCH*512];
__device__ float g_h2[BATCH*512];
__device__ float g_ft[BATCH*256];
__device__ float g_p1[BATCH*256];
__device__ float g_p2[BATCH*256];

// ---------------- weight prep: Wt[l][n'][k] ----------------
__global__ void prep_wt(const float* __restrict__ Ws, const float* __restrict__ Wn,
                        __nv_bfloat16* __restrict__ Wt){
    int idx = blockIdx.x * blockDim.x + threadIdx.x;
    int l = idx >> 15;
    int r = idx & 32767;
    int n = r >> 7;
    int k = r & 127;
    float v = (n < 128) ? Ws[l*16384 + k*128 + n] : Wn[l*16384 + k*128 + (n-128)];
    Wt[idx] = __float2bfloat16(v);
}

// ---------------- meta aggregation ----------------
__global__ void meta_agg(const __nv_bfloat16* __restrict__ X, const float* __restrict__ G,
                         int srcF32, __nv_bfloat16* __restrict__ MAgg){
    __shared__ float2 sm[16][64];
    int b = blockIdx.x, t = threadIdx.x;
    int f2 = t & 63, p = t >> 6;
    float2 s = make_float2(0.f, 0.f);
    int c0 = p * 64;
    if (srcF32) {
        const float2* gb = (const float2*)(G + (size_t)b * CELLS * FDIM);
        #pragma unroll 8
        for (int c = c0; c < c0 + 64; c++) {
            float2 v = gb[c*64 + f2];
            s.x += v.x; s.y += v.y;
        }
    } else {
        const __nv_bfloat162* xb = (const __nv_bfloat162*)(X + (size_t)b * XROWS * FDIM);
        #pragma unroll 8
        for (int c = c0; c < c0 + 64; c++) {
            float2 v = __bfloat1622float2(xb[c*64 + f2]);
            s.x += v.x; s.y += v.y;
        }
    }
    sm[p][f2] = s;
    __syncthreads();
    if (p == 0) {
        s = sm[0][f2];
        #pragma unroll
        for (int i = 1; i < 16; i++) { s.x += sm[i][f2].x; s.y += sm[i][f2].y; }
        ((__nv_bfloat162*)MAgg)[b*64 + f2] = __float22bfloat162_rn(s);
    }
}

// ---------------- dense GEMM: UV = A @ Wt^T (+bias on u-half) ----------------
// CTA tile 128x128, K=128 split into 2 cp.async stages (overlap fill/MMA).
// 512 threads = 16 warps (4m x 4n), warp 32x32. grid (1026, 2). 2 CTAs/SM.
#define STR2 272
#define SMB2_OFF (128*STR2)
#define GEMM_SMEM (256*STR2)   // 69632

__device__ __forceinline__ void ldmA(uint32_t addr, uint32_t* r){
    asm volatile("ldmatrix.sync.aligned.m8n8.x4.shared.b16 {%0,%1,%2,%3}, [%4];"
        : "=r"(r[0]), "=r"(r[1]), "=r"(r[2]), "=r"(r[3]) : "r"(addr));
}

__global__ void __launch_bounds__(512, 2) gnn_gemm(
    const __nv_bfloat16* __restrict__ X, const float* __restrict__ G, int srcF32,
    const __nv_bfloat16* __restrict__ MAgg,
    const __nv_bfloat16* __restrict__ Wt, const float* __restrict__ bias,
    __nv_bfloat16* __restrict__ UV)
{
    extern __shared__ char smem[];
    uint32_t sb = smem_u32(smem);
    int t = threadIdx.x;
    int wid = t >> 5, lane = t & 31;
    int m0cta = blockIdx.x * 128;
    int nhalf = blockIdx.y;

    // per-thread row & 32B-part assignment
    int rown = t >> 2;          // 0..127 (both A row m and B row n)
    int part = t & 3;           // 32-byte sub-slice within a 128B k-half
    int row  = m0cta + rown;
    int b    = row / GROWS;
    int node = row - b * GROWS;

    const char* bsrc = (const char*)(Wt + ((size_t)(nhalf*128 + rown))*128);
    uint32_t bdst = sb + SMB2_OFF + rown*STR2;
    uint32_t adst = sb + rown*STR2;

    // ---- two cp.async stages over K halves ----
    #pragma unroll
    for (int s = 0; s < 2; s++) {
        int kb = s*128 + part*32;          // byte offset within 256B row
        // B
        CP16(bdst + kb,      bsrc + kb);
        CP16(bdst + kb + 16, bsrc + kb + 16);
        // A
        if (node == GROWS - 1) {
            const uint4* src = (const uint4*)((const char*)(MAgg + b*FDIM) + kb);
            *(uint4*)(smem + rown*STR2 + kb)      = src[0];
            *(uint4*)(smem + rown*STR2 + kb + 16) = src[1];
        } else if (!srcF32) {
            const char* src = (const char*)(X + ((size_t)b * XROWS + node) * FDIM) + kb;
            CP16(adst + kb,      src);
            CP16(adst + kb + 16, src + 16);
        } else {
            if (node < CELLS) {
                const float* src = G + ((size_t)b * CELLS + node) * FDIM + (kb >> 1);
                #pragma unroll
                for (int j = 0; j < 2; j++) {
                    float4 v0 = *(const float4*)(src + j*8);
                    float4 v1 = *(const float4*)(src + j*8 + 4);
                    uint4 o;
                    __nv_bfloat162* ho = (__nv_bfloat162*)&o;
                    ho[0] = __float22bfloat162_rn(make_float2(v0.x, v0.y));
                    ho[1] = __float22bfloat162_rn(make_float2(v0.z, v0.w));
                    ho[2] = __float22bfloat162_rn(make_float2(v1.x, v1.y));
                    ho[3] = __float22bfloat162_rn(make_float2(v1.z, v1.w));
                    *(uint4*)(smem + rown*STR2 + kb + j*16) = o;
                }
            } else {   // meta node: x == 0 at layer 0
                uint4 z = make_uint4(0,0,0,0);
                *(uint4*)(smem + rown*STR2 + kb)      = z;
                *(uint4*)(smem + rown*STR2 + kb + 16) = z;
            }
        }
        CP_COMMIT();
    }

    // ---- MMA: 16 warps, warp tile 32x32; stage 0 overlapped with stage-1 fill ----
    int warp_m = wid >> 2;   // 0-3
    int warp_n = wid & 3;    // 0-3
    uint32_t saA = sb + (warp_m*32 + (lane & 15))*STR2 + (lane >> 4)*16;
    uint32_t saB = sb + SMB2_OFF + (warp_n*32 + (lane >> 4)*8 + (lane & 7))*STR2 + ((lane >> 3) & 1)*16;

    float acc[2][4][4];
    #pragma unroll
    for (int i = 0; i < 2; i++)
        #pragma unroll
        for (int j = 0; j < 4; j++)
            #pragma unroll
            for (int q = 0; q < 4; q++) acc[i][j][q] = 0.f;

    CP_WAIT(1);          // stage-0 data arrived
    __syncthreads();

    #pragma unroll
    for (int stage = 0; stage < 2; stage++) {
        if (stage == 1) {
            CP_WAIT(0);  // stage-1 data arrived
            __syncthreads();
        }
        #pragma unroll
        for (int ki = 0; ki < 4; ki++) {
            uint32_t ko = (stage*4 + ki) * 32;
            uint32_t a0[4], a1[4], b0[4], b1[4];
            ldmA(saA + ko, a0);
            ldmA(saA + 16*STR2 + ko, a1);
            ldmA(saB + ko, b0);
            ldmA(saB + 16*STR2 + ko, b1);
            uint32_t* afr[2] = { a0, a1 };
            uint32_t* bfr[2] = { b0, b1 };
            #pragma unroll
            for (int mf = 0; mf < 2; mf++)
                #pragma unroll
                for (int nf = 0; nf < 4; nf++) {
                    uint32_t rb0 = bfr[nf >> 1][(nf & 1)*2];
                    uint32_t rb1 = bfr[nf >> 1][(nf & 1)*2 + 1];
                    asm volatile("mma.sync.aligned.m16n8k16.row.col.f32.bf16.bf16.f32 "
                        "{%0,%1,%2,%3}, {%4,%5,%6,%7}, {%8,%9}, {%0,%1,%2,%3};"
                        : "+f"(acc[mf][nf][0]), "+f"(acc[mf][nf][1]),
                          "+f"(acc[mf][nf][2]), "+f"(acc[mf][nf][3])
                        : "r"(afr[mf][0]), "r"(afr[mf][1]), "r"(afr[mf][2]), "r"(afr[mf][3]),
                          "r"(rb0), "r"(rb1));
                }
        }
    }

    // ---- epilogue ----
    int gr = lane >> 2, gc = lane & 3;
    #pragma unroll
    for (int nf = 0; nf < 4; nf++) {
        int coln = warp_n*32 + nf*8 + 2*gc;
        float2 bb = make_float2(0.f, 0.f);
        if (nhalf == 0) bb = *(const float2*)(bias + coln);
        int colg = nhalf*128 + coln;
        #pragma unroll
        for (int mf = 0; mf < 2; mf++) {
            size_t r0 = (size_t)m0cta + warp_m*32 + mf*16 + gr;
            float v0 = acc[mf][nf][0] + bb.x;
            float v1 = acc[mf][nf][1] + bb.y;
            float v2 = acc[mf][nf][2] + bb.x;
            float v3 = acc[mf][nf][3] + bb.y;
            *(__nv_bfloat162*)(UV + r0 * 256 + colg)       = __float22bfloat162_rn(make_float2(v0, v1));
            *(__nv_bfloat162*)(UV + (r0 + 8) * 256 + colg) = __float22bfloat162_rn(make_float2(v2, v3));
        }
    }
}

// ---------------- stencil: y = elu(u + v[meta] + sum v[nbrs]), bf16 adds ----------------
__device__ __forceinline__ void badd8(const __nv_bfloat16* p, __nv_bfloat162* s){
    uint4 v = *(const uint4*)p;
    __nv_bfloat162* h = (__nv_bfloat162*)&v;
    #pragma unroll
    for (int i = 0; i < 4; i++) s[i] = __hadd2(s[i], h[i]);
}

__global__ void gnn_stencil(const __nv_bfloat16* __restrict__ UV, __nv_bfloat16* __restrict__ Y){
    int idx = blockIdx.x * blockDim.x + threadIdx.x;   // BATCH*XROWS*16
    int q = idx & 15;
    int nb = idx >> 4;
    int node = nb % XROWS;
    int b = nb / XROWS;
    const __nv_bfloat16* uvb = UV + (size_t)b * GROWS * 256;
    int qo = q * 8;

    __nv_bfloat162 s[4];
    {   // u
        uint4 v = *(const uint4*)(uvb + (size_t)node*256 + qo);
        __nv_bfloat162* h = (__nv_bfloat162*)&v;
        #pragma unroll
        for (int i = 0; i < 4; i++) s[i] = h[i];
    }
    const __nv_bfloat16* vb = uvb + 128 + qo;
    if (node < CELLS) {
        badd8(vb + (size_t)CELLS*256, s);       // v[meta]
        int r = node >> 5, c = node & 31;
        if (r > 0)  badd8(vb + (size_t)(node-32)*256, s);
        if (r < 31) badd8(vb + (size_t)(node+32)*256, s);
        if (c > 0)  badd8(vb + (size_t)(node-1)*256, s);
        if (c < 31) badd8(vb + (size_t)(node+1)*256, s);
    } else {
        badd8(vb + (size_t)(CELLS+1)*256, s);   // v[MAgg row]
    }
    uint4 o;
    __nv_bfloat162* ho = (__nv_bfloat162*)&o;
    #pragma unroll
    for (int i = 0; i < 4; i++) {
        float2 f = __bfloat1622float2(s[i]);
        ho[i] = __float22bfloat162_rn(make_float2(elu1(f.x), elu1(f.y)));
    }
    *(uint4*)(Y + ((size_t)b * XROWS + node) * FDIM + qo) = o;
}

// ---------------- gather 5 cells ----------------
__global__ void gather_state(const __nv_bfloat16* __restrict__ X, const int* __restrict__ pos,
                             float* __restrict__ state)
{
    int b = blockIdx.x;
    int f = threadIdx.x;
    int r = pos[2*b + 0];
    int c = pos[2*b + 1];
    const int dr[5] = {-1, 0, 1, 0, 0};
    const int dc[5] = { 0,-1, 0, 1, 0};
    #pragma unroll
    for (int o = 0; o < 5; o++) {
        int j  = (r + dr[o] + 1) * 32 + (c + dc[o] + 1);
        int jr = j / 34, jc = j % 34;
        float v = 0.f;
        if (jr >= 1 && jr <= 32 && jc >= 1 && jc <= 32) {
            int cell = (jr - 1) * 32 + (jc - 1);
            v = __bfloat162float(X[((size_t)b * XROWS + cell) * FDIM + f]);
        }
        state[b * 640 + o * FDIM + f] = v;
    }
}

// ---------------- small MLP GEMM (fp32, f32x2), tile 32x64 ----------------
template<bool ELU>
__global__ void __launch_bounds__(256) mlp_gemm(
    const float* __restrict__ A, const float* __restrict__ W,
    const float* __restrict__ bias, float* __restrict__ C, int K, int N)
{
    __shared__ float sAm[32][36];
    __shared__ float sWm[32][68];
    int t = threadIdx.x;
    int tx = t & 15;
    int ty = t >> 4;
    int m0 = blockIdx.y * 32;
    int n0 = blockIdx.x * 64;

    u64 acc[2][2];
    acc[0][0] = acc[0][1] = acc[1][0] = acc[1][1] = 0ULL;

    int arow = t >> 3, acg = t & 7;
    int wr = t >> 4, wn = (t & 15) * 4;

    for (int kk = 0; kk < K; kk += 32) {
        *(float4*)&sAm[arow][acg*4] = *(const float4*)(A + (size_t)(m0 + arow) * K + kk + acg*4);
        *(float4*)&sWm[wr][wn]      = *(const float4*)(W + (size_t)(kk + wr) * N + n0 + wn);
        *(float4*)&sWm[wr+16][wn]   = *(const float4*)(W + (size_t)(kk + wr + 16) * N + n0 + wn);
        __syncthreads();
        #pragma unroll
        for (int k = 0; k < 32; k++) {
            F2 b0, b1;
            b0.f = *(const float2*)&sWm[k][tx*4];
            b1.f = *(const float2*)&sWm[k][tx*4 + 2];
            #pragma unroll
            for (int i = 0; i < 2; i++) {
                float av = sAm[ty*2+i][k];
                u64 ap = pack2(av, av);
                ffma2(acc[i][0], ap, b0.u);
                ffma2(acc[i][1], ap, b1.u);
            }
        }
        __syncthreads();
    }

    float4 bb = *(const float4*)(bias + n0 + tx*4);
    #pragma unroll
    for (int i = 0; i < 2; i++) {
        F2 u0, u1; u0.u = acc[i][0]; u1.u = acc[i][1];
        float4 o;
        o.x = u0.f.x + bb.x; o.y = u0.f.y + bb.y;
        o.z = u1.f.x + bb.z; o.w = u1.f.y + bb.w;
        if (ELU) { o.x = elu1(o.x); o.y = elu1(o.y); o.z = elu1(o.z); o.w = elu1(o.w); }
        *(float4*)(C + (size_t)(m0 + ty*2 + i) * N + n0 + tx*4) = o;
    }
}

// ---------------- logits + mask ----------------
__global__ void logits_k(const float* __restrict__ P2, const float* __restrict__ W,
                         const float* __restrict__ bias, const int* __restrict__ mask,
                         float* __restrict__ out)
{
    int b = blockIdx.x;
    int a = threadIdx.x;
    if (a >= 19) return;
    float s = bias[a];
    const float* p = P2 + b * 256;
    #pragma unroll 8
    for (int k = 0; k < 256; k++) s += p[k] * W[k * 19 + a];
    int m = mask[b * 19 + a];
    out[b * 19 + a] = s + (m > 0 ? 0.f : -3.4028234663852886e38f);
}

// ---------------- launch ----------------
extern "C" void kernel_launch(void* const* d_in, const int* in_sizes, int n_in,
                              void* d_out, int out_size)
{
    const float* gmap  = (const float*)d_in[0];
    const int*   pos   = (const int*)  d_in[1];
    const int*   amask = (const int*)  d_in[2];
    const float* Ws    = (const float*)d_in[3];
    const float* Wn    = (const float*)d_in[4];
    const float* bs    = (const float*)d_in[5];
    const float* W_d1  = (const float*)d_in[6];
    const float* b_d1  = (const float*)d_in[7];
    const float* W_d2  = (const float*)d_in[8];
    const float* b_d2  = (const float*)d_in[9];
    const float* W_d3  = (const float*)d_in[10];
    const float* b_d3  = (const float*)d_in[11];
    const float* W_p1  = (const float*)d_in[12];
    const float* b_p1  = (const float*)d_in[13];
    const float* W_p2  = (const float*)d_in[14];
    const float* b_p2  = (const float*)d_in[15];
    const float* W_p3  = (const float*)d_in[16];
    const float* b_p3  = (const float*)d_in[17];
    float* out = (float*)d_out;

    __nv_bfloat16 *x0, *x1, *uv, *ma, *wt;
    float *st, *h1, *h2, *ft, *p1, *p2;
    cudaGetSymbolAddress((void**)&x0, g_xb0);
    cudaGetSymbolAddress((void**)&x1, g_xb1);
    cudaGetSymbolAddress((void**)&uv, g_uv);
    cudaGetSymbolAddress((void**)&ma, g_magg);
    cudaGetSymbolAddress((void**)&wt, g_wt);
    cudaGetSymbolAddress((void**)&st, g_state);
    cudaGetSymbolAddress((void**)&h1, g_h1);
    cudaGetSymbolAddress((void**)&h2, g_h2);
    cudaGetSymbolAddress((void**)&ft, g_ft);
    cudaGetSymbolAddress((void**)&p1, g_p1);
    cudaGetSymbolAddress((void**)&p2, g_p2);

    cudaFuncSetAttribute(gnn_gemm, cudaFuncAttributeMaxDynamicSharedMemorySize, GEMM_SMEM);

    prep_wt<<<(3*256*128)/256, 256>>>(Ws, Wn, wt);

    dim3 gg(MTOT/128, 2);
    // layer 0 (A from gmap fp32)
    meta_agg<<<BATCH, 1024>>>(nullptr, gmap, 1, ma);
    gnn_gemm<<<gg, 512, GEMM_SMEM>>>(nullptr, gmap, 1, ma, wt, bs, uv);
    gnn_stencil<<<(BATCH*XROWS*16)/256, 256>>>(uv, x0);
    // layer 1
    meta_agg<<<BATCH, 1024>>>(x0, nullptr, 0, ma);
    gnn_gemm<<<gg, 512, GEMM_SMEM>>>(x0, nullptr, 0, ma, wt + 256*128, bs + 128, uv);
    gnn_stencil<<<(BATCH*XROWS*16)/256, 256>>>(uv, x1);
    // layer 2
    meta_agg<<<BATCH, 1024>>>(x1, nullptr, 0, ma);
    gnn_gemm<<<gg, 512, GEMM_SMEM>>>(x1, nullptr, 0, ma, wt + 2*256*128, bs + 256, uv);
    gnn_stencil<<<(BATCH*XROWS*16)/256, 256>>>(uv, x0);

    gather_state<<<BATCH, 128>>>(x0, pos, st);

    mlp_gemm<true><<<dim3(8, 4), 256>>>(st, W_d1, b_d1, h1, 640, 512);
    mlp_gemm<true><<<dim3(8, 4), 256>>>(h1, W_d2, b_d2, h2, 512, 512);
    mlp_gemm<true><<<dim3(4, 4), 256>>>(h2, W_d3, b_d3, ft, 512, 256);
    mlp_gemm<true><<<dim3(4, 4), 256>>>(ft, W_p1, b_p1, p1, 256, 256);
    mlp_gemm<true><<<dim3(4, 4), 256>>>(p1, W_p2, b_p2, p2, 256, 256);

    logits_k<<<BATCH, 32>>>(p2, W_p3, b_p3, amask, out);
}